// round 3
// baseline (speedup 1.0000x reference)
#include <cuda_runtime.h>
#include <cuda_bf16.h>
#include <stdint.h>

#define S_LEN  512
#define BATCH  32
#define NSPAN  131072
#define MROWS  16384   // S*B
#define KDIM   1024
#define NDIM   512

#define BM 128
#define BN 128
#define BK 32
#define LDSB 40   // smem row stride in bf16 (32 + 8 pad, keeps 16B alignment)

#define SPW 16   // spans per warp in span_kernel
#define SPAN_BLOCKS (NSPAN / (8 * SPW))   // 1024

// ---- scratch (static device globals; no runtime allocation) ----
__device__ __align__(256) __nv_bfloat16 g_W[(size_t)NDIM*KDIM];   //  1 MB: W'[n][k]
__device__ __align__(256) __nv_bfloat16 g_P[(size_t)MROWS*NDIM];  // 16 MB: P[m][n]
__device__ float g_part[SPAN_BLOCKS*3];

// ---------------- W' = [W1_top ; -W1_bot] transposed -> bf16 [n][k] ----------------
__global__ void conv_w_kernel(const float* __restrict__ W1){
  unsigned idx = blockIdx.x*256u + threadIdx.x;  // 512*1024
  unsigned n = idx & 511u;
  unsigned k = idx >> 9;
  float v = W1[(size_t)k*512u + n];
  if (k >= 512u) v = -v;
  g_W[(size_t)n*1024u + k] = __float2bfloat16(v);
}

// ---------------- bf16 mma.sync GEMM: P = A2 @ W'^T, A2 built on the fly ----------------
__device__ __forceinline__ void mma_bf16(float* d, const uint32_t* a, const uint32_t* b){
  asm volatile(
    "mma.sync.aligned.m16n8k16.row.col.f32.bf16.bf16.f32 "
    "{%0,%1,%2,%3}, {%4,%5,%6,%7}, {%8,%9}, {%0,%1,%2,%3};\n"
    : "+f"(d[0]), "+f"(d[1]), "+f"(d[2]), "+f"(d[3])
    : "r"(a[0]), "r"(a[1]), "r"(a[2]), "r"(a[3]), "r"(b[0]), "r"(b[1]));
}
__device__ __forceinline__ void ldsm_x4(uint32_t* r, uint32_t addr){
  asm volatile("ldmatrix.sync.aligned.m8n8.x4.shared.b16 {%0,%1,%2,%3}, [%4];\n"
    : "=r"(r[0]), "=r"(r[1]), "=r"(r[2]), "=r"(r[3]) : "r"(addr));
}
__device__ __forceinline__ void ldsm_x2(uint32_t* r, uint32_t addr){
  asm volatile("ldmatrix.sync.aligned.m8n8.x2.shared.b16 {%0,%1}, [%2];\n"
    : "=r"(r[0]), "=r"(r[1]) : "r"(addr));
}
__device__ __forceinline__ uint4 ldcvt8(const float* __restrict__ p){
  float4 a = *reinterpret_cast<const float4*>(p);
  float4 b = *reinterpret_cast<const float4*>(p+4);
  __nv_bfloat162 t0 = __floats2bfloat162_rn(a.x, a.y);
  __nv_bfloat162 t1 = __floats2bfloat162_rn(a.z, a.w);
  __nv_bfloat162 t2 = __floats2bfloat162_rn(b.x, b.y);
  __nv_bfloat162 t3 = __floats2bfloat162_rn(b.z, b.w);
  uint4 r;
  r.x = *reinterpret_cast<uint32_t*>(&t0);
  r.y = *reinterpret_cast<uint32_t*>(&t1);
  r.z = *reinterpret_cast<uint32_t*>(&t2);
  r.w = *reinterpret_cast<uint32_t*>(&t3);
  return r;
}

__global__ __launch_bounds__(256) void gemm_kernel(const float* __restrict__ hidden){
  __shared__ __nv_bfloat16 As[BM*LDSB];
  __shared__ __nv_bfloat16 Bs[BN*LDSB];
  const int tid = threadIdx.x;
  const __nv_bfloat16* __restrict__ Bg = g_W + (size_t)blockIdx.x*BN*KDIM;

  const int lrow = tid >> 2;           // 0..63
  const int lcol = (tid & 3) * 8;      // 0,8,16,24

  const int lane = tid & 31;
  const int w    = tid >> 5;
  const int wm   = w & 1;    // 2 warps along M (64 rows each)
  const int wn   = w >> 1;   // 4 warps along N (32 cols each)

  // A source rows (fp32 hidden), with the r-1 shift for the first K-half
  const int m0 = blockIdx.y*BM + lrow;
  const int r0 = m0 >> 5, bb0 = m0 & 31;
  const int m1 = m0 + 64;
  const int r1 = m1 >> 5, bb1 = m1 & 31;       // r1 = r0+2 >= 2 always
  const float* __restrict__ h0a = hidden + ((size_t)((r0-1)*32 + bb0))*1024u; // k<512
  const float* __restrict__ h0b = hidden + ((size_t)(r0*32 + bb0))*1024u;     // k>=512
  const float* __restrict__ h1a = hidden + ((size_t)((r1-1)*32 + bb1))*1024u;
  const float* __restrict__ h1b = hidden + ((size_t)(r1*32 + bb1))*1024u;
  const bool row0_zero_fh = (r0 == 0);

  uint32_t as_base = (uint32_t)__cvta_generic_to_shared(As);
  uint32_t bs_base = (uint32_t)__cvta_generic_to_shared(Bs);
  const int a_row = wm*64 + (lane & 15);
  const int a_ch  = ((lane >> 4) << 3);
  uint32_t a_lm = as_base + (uint32_t)(a_row*LDSB + a_ch)*2u;
  const int b_row = wn*32 + (lane & 7);
  const int b_ch  = (((lane >> 3) & 1) << 3);
  uint32_t b_lm = bs_base + (uint32_t)(b_row*LDSB + b_ch)*2u;

  float acc[4][4][4];
  #pragma unroll
  for (int i=0;i<4;i++)
    #pragma unroll
    for (int j=0;j<4;j++)
      #pragma unroll
      for (int q=0;q<4;q++) acc[i][j][q]=0.f;

  uint4 av0, av1, bv0, bv1;
  {
    const int c = lcol;   // k0 = 0, first half
    av0 = make_uint4(0u,0u,0u,0u);
    if (!row0_zero_fh) av0 = ldcvt8(h0a + c);
    av1 = ldcvt8(h1a + c);
    bv0 = *reinterpret_cast<const uint4*>(Bg + (size_t)lrow*KDIM + c);
    bv1 = *reinterpret_cast<const uint4*>(Bg + (size_t)(lrow+64)*KDIM + c);
  }

  for (int k0 = 0; k0 < KDIM; k0 += BK){
    *reinterpret_cast<uint4*>(&As[lrow*LDSB + lcol])      = av0;
    *reinterpret_cast<uint4*>(&As[(lrow+64)*LDSB + lcol]) = av1;
    *reinterpret_cast<uint4*>(&Bs[lrow*LDSB + lcol])      = bv0;
    *reinterpret_cast<uint4*>(&Bs[(lrow+64)*LDSB + lcol]) = bv1;
    __syncthreads();
    if (k0 + BK < KDIM){
      const int c = k0 + BK + lcol;
      const bool fh = (c < 512);
      if (fh){
        av0 = make_uint4(0u,0u,0u,0u);
        if (!row0_zero_fh) av0 = ldcvt8(h0a + c);
        av1 = ldcvt8(h1a + c);
      } else {
        av0 = ldcvt8(h0b + c);
        av1 = ldcvt8(h1b + c);
      }
      bv0 = *reinterpret_cast<const uint4*>(Bg + (size_t)lrow*KDIM + c);
      bv1 = *reinterpret_cast<const uint4*>(Bg + (size_t)(lrow+64)*KDIM + c);
    }
    #pragma unroll
    for (int kk = 0; kk < 2; kk++){
      uint32_t af[4][4];
      #pragma unroll
      for (int mt=0; mt<4; mt++)
        ldsm_x4(af[mt], a_lm + (uint32_t)(mt*16*LDSB*2) + (uint32_t)kk*32u);
      uint32_t bf[4][2];
      #pragma unroll
      for (int nt=0; nt<4; nt++)
        ldsm_x2(bf[nt], b_lm + (uint32_t)(nt*8*LDSB*2) + (uint32_t)kk*32u);
      #pragma unroll
      for (int mt=0; mt<4; mt++)
        #pragma unroll
        for (int nt=0; nt<4; nt++)
          mma_bf16(acc[mt][nt], af[mt], bf[nt]);
    }
    __syncthreads();
  }

  const int rbase = blockIdx.y*BM + wm*64;
  const int cbase = blockIdx.x*BN + wn*32;
  #pragma unroll
  for (int mt=0; mt<4; mt++){
    int r0o = rbase + mt*16 + (lane >> 2);
    #pragma unroll
    for (int nt=0; nt<4; nt++){
      int cc = cbase + nt*8 + (lane & 3)*2;
      __nv_bfloat162 v0 = __floats2bfloat162_rn(acc[mt][nt][0], acc[mt][nt][1]);
      __nv_bfloat162 v1 = __floats2bfloat162_rn(acc[mt][nt][2], acc[mt][nt][3]);
      *reinterpret_cast<__nv_bfloat162*>(g_P + (size_t)r0o*NDIM + cc)     = v0;
      *reinterpret_cast<__nv_bfloat162*>(g_P + (size_t)(r0o+8)*NDIM + cc) = v1;
    }
  }
}

// ---------------- span pass: 16 spans/warp, b1+W2 in registers ----------------
__device__ __forceinline__ float proc8(uint4 e, uint4 q,
                                        const float* __restrict__ bb,
                                        const float* __restrict__ ww, float acc){
  const uint32_t* pe = &e.x;
  const uint32_t* pq = &q.x;
  #pragma unroll
  for (int i=0;i<4;i++){
    float elo = __int_as_float(pe[i] << 16);
    float ehi = __int_as_float(pe[i] & 0xFFFF0000u);
    float qlo = __int_as_float(pq[i] << 16);
    float qhi = __int_as_float(pq[i] & 0xFFFF0000u);
    acc = fmaf(fmaxf(elo - qlo + bb[2*i],   0.f), ww[2*i],   acc);
    acc = fmaf(fmaxf(ehi - qhi + bb[2*i+1], 0.f), ww[2*i+1], acc);
  }
  return acc;
}

__global__ __launch_bounds__(256) void span_kernel(
    const int* __restrict__ bids, const int* __restrict__ begins,
    const int* __restrict__ ends, const int* __restrict__ flags,
    const float* __restrict__ wts, const float* __restrict__ b1,
    const float* __restrict__ W2, const float* __restrict__ b2)
{
  __shared__ float s_red[8][3];
  const int lane = threadIdx.x & 31;
  const int wrp  = threadIdx.x >> 5;
  const int n0   = (blockIdx.x*8 + wrp)*SPW;

  // per-lane constants: columns [8*lane, 8*lane+8) and [256+8*lane, 256+8*lane+8)
  float b1r[16], w2r[16];
  {
    const float4* B1 = reinterpret_cast<const float4*>(b1);
    const float4* Wv = reinterpret_cast<const float4*>(W2);
    float4 t;
    t = B1[2*lane];    b1r[0]=t.x;  b1r[1]=t.y;  b1r[2]=t.z;  b1r[3]=t.w;
    t = B1[2*lane+1];  b1r[4]=t.x;  b1r[5]=t.y;  b1r[6]=t.z;  b1r[7]=t.w;
    t = B1[2*lane+64]; b1r[8]=t.x;  b1r[9]=t.y;  b1r[10]=t.z; b1r[11]=t.w;
    t = B1[2*lane+65]; b1r[12]=t.x; b1r[13]=t.y; b1r[14]=t.z; b1r[15]=t.w;
    t = Wv[2*lane];    w2r[0]=t.x;  w2r[1]=t.y;  w2r[2]=t.z;  w2r[3]=t.w;
    t = Wv[2*lane+1];  w2r[4]=t.x;  w2r[5]=t.y;  w2r[6]=t.z;  w2r[7]=t.w;
    t = Wv[2*lane+64]; w2r[8]=t.x;  w2r[9]=t.y;  w2r[10]=t.z; w2r[11]=t.w;
    t = Wv[2*lane+65]; w2r[12]=t.x; w2r[13]=t.y; w2r[14]=t.z; w2r[15]=t.w;
  }
  const float b2v = b2[0];

  float logit_keep = 0.f;
  #pragma unroll
  for (int s = 0; s < SPW; s += 2){
    const int na = n0 + s, nb = n0 + s + 1;
    const int ia = bids[na], ga = begins[na], ea = ends[na];
    const int ib = bids[nb], gb = begins[nb], eb = ends[nb];
    const uint4* PeA = reinterpret_cast<const uint4*>(g_P + ((size_t)(ea*32+ia))*512u);
    const uint4* PgA = reinterpret_cast<const uint4*>(g_P + ((size_t)(ga*32+ia))*512u);
    const uint4* PeB = reinterpret_cast<const uint4*>(g_P + ((size_t)(eb*32+ib))*512u);
    const uint4* PgB = reinterpret_cast<const uint4*>(g_P + ((size_t)(gb*32+ib))*512u);
    uint4 a0 = PeA[lane], a1 = PeA[lane+32];
    uint4 c0 = PgA[lane], c1 = PgA[lane+32];
    uint4 d0 = PeB[lane], d1 = PeB[lane+32];
    uint4 f0 = PgB[lane], f1 = PgB[lane+32];
    float acca = proc8(a0, c0, b1r,   w2r,   0.f);
    acca       = proc8(a1, c1, b1r+8, w2r+8, acca);
    float accb = proc8(d0, f0, b1r,   w2r,   0.f);
    accb       = proc8(d1, f1, b1r+8, w2r+8, accb);
    #pragma unroll
    for (int off=16; off>0; off>>=1){
      acca += __shfl_xor_sync(0xffffffffu, acca, off);
      accb += __shfl_xor_sync(0xffffffffu, accb, off);
    }
    if (lane == s)   logit_keep = acca;
    if (lane == s+1) logit_keep = accb;
  }

  // lanes 0..SPW-1 each own one span's logit
  float sp = 0.f, sn = 0.f, sc = 0.f;
  if (lane < SPW){
    const int n = n0 + lane;
    float logit = logit_keep + b2v;
    float pp = 1.f / (1.f + expf(-logit));
    pp = fminf(fmaxf(pp, 1e-7f), 1.f - 1e-7f);
    int fl = flags[n];
    float wgt = wts[n];
    float bce = (fl == 1) ? -logf(pp) : -logf(1.f - pp);
    sp = (fl == 1) ? wgt*bce : 0.f;
    sn = (fl == 1) ? 0.f : wgt*bce;
    sc = (fl == 1) ? 1.f : 0.f;
  }
  #pragma unroll
  for (int off=16; off>0; off>>=1){
    sp += __shfl_xor_sync(0xffffffffu, sp, off);
    sn += __shfl_xor_sync(0xffffffffu, sn, off);
    sc += __shfl_xor_sync(0xffffffffu, sc, off);
  }
  if (lane == 0){ s_red[wrp][0]=sp; s_red[wrp][1]=sn; s_red[wrp][2]=sc; }
  __syncthreads();
  if (threadIdx.x == 0){
    float a=0.f,b=0.f,c=0.f;
    #pragma unroll
    for (int i=0;i<8;i++){ a+=s_red[i][0]; b+=s_red[i][1]; c+=s_red[i][2]; }
    g_part[blockIdx.x*3+0]=a;
    g_part[blockIdx.x*3+1]=b;
    g_part[blockIdx.x*3+2]=c;
  }
}

// ---------------- deterministic final reduction ----------------
__global__ void finalize_kernel(float* __restrict__ out){
  __shared__ float sp[256], sn[256], sc[256];
  int t = threadIdx.x;
  float a=0.f, b=0.f, c=0.f;
  for (int i=t; i<SPAN_BLOCKS; i+=256){
    a += g_part[i*3+0];
    b += g_part[i*3+1];
    c += g_part[i*3+2];
  }
  sp[t]=a; sn[t]=b; sc[t]=c;
  __syncthreads();
  for (int s=128; s>0; s>>=1){
    if (t < s){ sp[t]+=sp[t+s]; sn[t]+=sn[t+s]; sc[t]+=sc[t+s]; }
    __syncthreads();
  }
  if (t==0){
    const float Nf = 131072.f;
    float scale = 2.f*sc[0]/Nf;
    out[0] = (sp[0] + scale*sn[0]) / Nf;
  }
}

// ---------------- launch ----------------
extern "C" void kernel_launch(void* const* d_in, const int* in_sizes, int n_in,
                              void* d_out, int out_size){
  const float* hidden = (const float*)d_in[0];
  const int* bids     = (const int*)d_in[1];
  const int* begins   = (const int*)d_in[2];
  const int* ends     = (const int*)d_in[3];
  const int* flags    = (const int*)d_in[4];
  const float* wts    = (const float*)d_in[5];
  const float* W1     = (const float*)d_in[6];
  const float* b1     = (const float*)d_in[7];
  const float* W2     = (const float*)d_in[8];
  const float* b2     = (const float*)d_in[9];

  conv_w_kernel<<<2048, 256>>>(W1);
  gemm_kernel<<<dim3(NDIM/BN, MROWS/BM), 256>>>(hidden);
  span_kernel<<<SPAN_BLOCKS, 256>>>(bids, begins, ends, flags, wts, b1, W2, b2);
  finalize_kernel<<<1, 256>>>((float*)d_out);
}

// round 4
// speedup vs baseline: 1.3329x; 1.3329x over previous
#include <cuda_runtime.h>
#include <cuda_bf16.h>
#include <stdint.h>

#define S_LEN  512
#define BATCH  32
#define NSPAN  131072
#define MROWS  16384   // S*B
#define KDIM   1024
#define NDIM   512

#define BM 128
#define BN 128
#define BK 32
#define LDSB 40   // smem row stride in bf16 (32 + 8 pad, keeps 16B alignment)

#define SPW 16   // spans per warp in span_kernel
#define SPAN_BLOCKS (NSPAN / (8 * SPW))   // 1024

// ---- scratch (static device globals; no runtime allocation) ----
__device__ __align__(256) __nv_bfloat16 g_A[(size_t)MROWS*KDIM];  // 32 MB: A2[m][k]
__device__ __align__(256) __nv_bfloat16 g_W[(size_t)NDIM*KDIM];   //  1 MB: W'[n][k]
__device__ __align__(256) __nv_bfloat16 g_P[(size_t)MROWS*NDIM];  // 16 MB: P[m][n]
__device__ float g_part[SPAN_BLOCKS*3];

// ---------------- build A2 = [Hf[r-1] , Hb[r]] in bf16 (one pass) ----------------
__global__ void conv_hidden_kernel(const float* __restrict__ hidden){
  unsigned idx = blockIdx.x*256u + threadIdx.x;   // 16384*128
  unsigned c8 = idx & 127u;        // 8-col group
  unsigned m  = idx >> 7;          // row 0..16383
  unsigned r  = m >> 5;
  unsigned b  = m & 31u;
  unsigned col = c8 * 8u;
  __nv_bfloat162 o0, o1, o2, o3;
  if (col < 512u){
    if (r == 0u){
      o0 = o1 = o2 = o3 = __floats2bfloat162_rn(0.f, 0.f);
    } else {
      const float4* src = reinterpret_cast<const float4*>(
          hidden + ((size_t)(r-1u)*32u + b)*1024u + col);
      float4 v0 = src[0], v1 = src[1];
      o0 = __floats2bfloat162_rn(v0.x, v0.y);
      o1 = __floats2bfloat162_rn(v0.z, v0.w);
      o2 = __floats2bfloat162_rn(v1.x, v1.y);
      o3 = __floats2bfloat162_rn(v1.z, v1.w);
    }
  } else {
    const float4* src = reinterpret_cast<const float4*>(
        hidden + ((size_t)r*32u + b)*1024u + col);
    float4 v0 = src[0], v1 = src[1];
    o0 = __floats2bfloat162_rn(v0.x, v0.y);
    o1 = __floats2bfloat162_rn(v0.z, v0.w);
    o2 = __floats2bfloat162_rn(v1.x, v1.y);
    o3 = __floats2bfloat162_rn(v1.z, v1.w);
  }
  uint4 pack;
  pack.x = *reinterpret_cast<uint32_t*>(&o0);
  pack.y = *reinterpret_cast<uint32_t*>(&o1);
  pack.z = *reinterpret_cast<uint32_t*>(&o2);
  pack.w = *reinterpret_cast<uint32_t*>(&o3);
  *reinterpret_cast<uint4*>(g_A + (size_t)m*1024u + col) = pack;
}

// ---------------- W' = [W1_top ; -W1_bot] transposed -> bf16 [n][k] ----------------
__global__ void conv_w_kernel(const float* __restrict__ W1){
  unsigned idx = blockIdx.x*256u + threadIdx.x;  // 512*1024
  unsigned n = idx & 511u;
  unsigned k = idx >> 9;
  float v = W1[(size_t)k*512u + n];
  if (k >= 512u) v = -v;
  g_W[(size_t)n*1024u + k] = __float2bfloat16(v);
}

// ---------------- bf16 mma.sync GEMM: P = A2 @ W'^T ----------------
__device__ __forceinline__ void mma_bf16(float* d, const uint32_t* a, const uint32_t* b){
  asm volatile(
    "mma.sync.aligned.m16n8k16.row.col.f32.bf16.bf16.f32 "
    "{%0,%1,%2,%3}, {%4,%5,%6,%7}, {%8,%9}, {%0,%1,%2,%3};\n"
    : "+f"(d[0]), "+f"(d[1]), "+f"(d[2]), "+f"(d[3])
    : "r"(a[0]), "r"(a[1]), "r"(a[2]), "r"(a[3]), "r"(b[0]), "r"(b[1]));
}
__device__ __forceinline__ void ldsm_x4(uint32_t* r, uint32_t addr){
  asm volatile("ldmatrix.sync.aligned.m8n8.x4.shared.b16 {%0,%1,%2,%3}, [%4];\n"
    : "=r"(r[0]), "=r"(r[1]), "=r"(r[2]), "=r"(r[3]) : "r"(addr));
}
__device__ __forceinline__ void ldsm_x2(uint32_t* r, uint32_t addr){
  asm volatile("ldmatrix.sync.aligned.m8n8.x2.shared.b16 {%0,%1}, [%2];\n"
    : "=r"(r[0]), "=r"(r[1]) : "r"(addr));
}

__global__ __launch_bounds__(256,1) void gemm_kernel(){
  __shared__ __nv_bfloat16 As[BM*LDSB];
  __shared__ __nv_bfloat16 Bs[BN*LDSB];
  const int tid = threadIdx.x;
  const __nv_bfloat16* __restrict__ Ag = g_A + (size_t)blockIdx.y*BM*KDIM;
  const __nv_bfloat16* __restrict__ Bg = g_W + (size_t)blockIdx.x*BN*KDIM;

  const int lrow = tid >> 2;           // 0..63
  const int lcol = (tid & 3) * 8;      // 0,8,16,24

  const int lane = tid & 31;
  const int w    = tid >> 5;
  const int wm   = w & 1;    // 2 warps along M (64 rows each)
  const int wn   = w >> 1;   // 4 warps along N (32 cols each)

  uint32_t as_base = (uint32_t)__cvta_generic_to_shared(As);
  uint32_t bs_base = (uint32_t)__cvta_generic_to_shared(Bs);
  const int a_row = wm*64 + (lane & 15);
  const int a_ch  = ((lane >> 4) << 3);
  uint32_t a_lm = as_base + (uint32_t)(a_row*LDSB + a_ch)*2u;
  const int b_row = wn*32 + (lane & 7);
  const int b_ch  = (((lane >> 3) & 1) << 3);
  uint32_t b_lm = bs_base + (uint32_t)(b_row*LDSB + b_ch)*2u;

  float acc[4][4][4];
  #pragma unroll
  for (int i=0;i<4;i++)
    #pragma unroll
    for (int j=0;j<4;j++)
      #pragma unroll
      for (int q=0;q<4;q++) acc[i][j][q]=0.f;

  uint4 av0 = *reinterpret_cast<const uint4*>(Ag + (size_t)lrow*KDIM + lcol);
  uint4 av1 = *reinterpret_cast<const uint4*>(Ag + (size_t)(lrow+64)*KDIM + lcol);
  uint4 bv0 = *reinterpret_cast<const uint4*>(Bg + (size_t)lrow*KDIM + lcol);
  uint4 bv1 = *reinterpret_cast<const uint4*>(Bg + (size_t)(lrow+64)*KDIM + lcol);

  for (int k0 = 0; k0 < KDIM; k0 += BK){
    *reinterpret_cast<uint4*>(&As[lrow*LDSB + lcol])      = av0;
    *reinterpret_cast<uint4*>(&As[(lrow+64)*LDSB + lcol]) = av1;
    *reinterpret_cast<uint4*>(&Bs[lrow*LDSB + lcol])      = bv0;
    *reinterpret_cast<uint4*>(&Bs[(lrow+64)*LDSB + lcol]) = bv1;
    __syncthreads();
    if (k0 + BK < KDIM){
      av0 = *reinterpret_cast<const uint4*>(Ag + (size_t)lrow*KDIM + (k0+BK) + lcol);
      av1 = *reinterpret_cast<const uint4*>(Ag + (size_t)(lrow+64)*KDIM + (k0+BK) + lcol);
      bv0 = *reinterpret_cast<const uint4*>(Bg + (size_t)lrow*KDIM + (k0+BK) + lcol);
      bv1 = *reinterpret_cast<const uint4*>(Bg + (size_t)(lrow+64)*KDIM + (k0+BK) + lcol);
    }
    #pragma unroll
    for (int kk = 0; kk < 2; kk++){
      uint32_t af[4][4];
      #pragma unroll
      for (int mt=0; mt<4; mt++)
        ldsm_x4(af[mt], a_lm + (uint32_t)(mt*16*LDSB*2) + (uint32_t)kk*32u);
      uint32_t bf[4][2];
      #pragma unroll
      for (int nt=0; nt<4; nt++)
        ldsm_x2(bf[nt], b_lm + (uint32_t)(nt*8*LDSB*2) + (uint32_t)kk*32u);
      #pragma unroll
      for (int mt=0; mt<4; mt++)
        #pragma unroll
        for (int nt=0; nt<4; nt++)
          mma_bf16(acc[mt][nt], af[mt], bf[nt]);
    }
    __syncthreads();
  }

  const int rbase = blockIdx.y*BM + wm*64;
  const int cbase = blockIdx.x*BN + wn*32;
  #pragma unroll
  for (int mt=0; mt<4; mt++){
    int r0 = rbase + mt*16 + (lane >> 2);
    #pragma unroll
    for (int nt=0; nt<4; nt++){
      int cc = cbase + nt*8 + (lane & 3)*2;
      __nv_bfloat162 v0 = __floats2bfloat162_rn(acc[mt][nt][0], acc[mt][nt][1]);
      __nv_bfloat162 v1 = __floats2bfloat162_rn(acc[mt][nt][2], acc[mt][nt][3]);
      *reinterpret_cast<__nv_bfloat162*>(g_P + (size_t)r0*NDIM + cc)     = v0;
      *reinterpret_cast<__nv_bfloat162*>(g_P + (size_t)(r0+8)*NDIM + cc) = v1;
    }
  }
}

// ---------------- span pass: 16 spans/warp, b1+W2 in registers ----------------
__device__ __forceinline__ float proc8(uint4 e, uint4 q,
                                        const float* __restrict__ bb,
                                        const float* __restrict__ ww, float acc){
  const uint32_t* pe = &e.x;
  const uint32_t* pq = &q.x;
  #pragma unroll
  for (int i=0;i<4;i++){
    float elo = __int_as_float(pe[i] << 16);
    float ehi = __int_as_float(pe[i] & 0xFFFF0000u);
    float qlo = __int_as_float(pq[i] << 16);
    float qhi = __int_as_float(pq[i] & 0xFFFF0000u);
    acc = fmaf(fmaxf(elo - qlo + bb[2*i],   0.f), ww[2*i],   acc);
    acc = fmaf(fmaxf(ehi - qhi + bb[2*i+1], 0.f), ww[2*i+1], acc);
  }
  return acc;
}

__global__ __launch_bounds__(256) void span_kernel(
    const int* __restrict__ bids, const int* __restrict__ begins,
    const int* __restrict__ ends, const int* __restrict__ flags,
    const float* __restrict__ wts, const float* __restrict__ b1,
    const float* __restrict__ W2, const float* __restrict__ b2)
{
  __shared__ float s_red[8][3];
  const int lane = threadIdx.x & 31;
  const int wrp  = threadIdx.x >> 5;
  const int n0   = (blockIdx.x*8 + wrp)*SPW;

  // per-lane constants: columns [8*lane, 8*lane+8) and [256+8*lane, 256+8*lane+8)
  float b1r[16], w2r[16];
  {
    const float4* B1 = reinterpret_cast<const float4*>(b1);
    const float4* Wv = reinterpret_cast<const float4*>(W2);
    float4 t;
    t = B1[2*lane];    b1r[0]=t.x;  b1r[1]=t.y;  b1r[2]=t.z;  b1r[3]=t.w;
    t = B1[2*lane+1];  b1r[4]=t.x;  b1r[5]=t.y;  b1r[6]=t.z;  b1r[7]=t.w;
    t = B1[2*lane+64]; b1r[8]=t.x;  b1r[9]=t.y;  b1r[10]=t.z; b1r[11]=t.w;
    t = B1[2*lane+65]; b1r[12]=t.x; b1r[13]=t.y; b1r[14]=t.z; b1r[15]=t.w;
    t = Wv[2*lane];    w2r[0]=t.x;  w2r[1]=t.y;  w2r[2]=t.z;  w2r[3]=t.w;
    t = Wv[2*lane+1];  w2r[4]=t.x;  w2r[5]=t.y;  w2r[6]=t.z;  w2r[7]=t.w;
    t = Wv[2*lane+64]; w2r[8]=t.x;  w2r[9]=t.y;  w2r[10]=t.z; w2r[11]=t.w;
    t = Wv[2*lane+65]; w2r[12]=t.x; w2r[13]=t.y; w2r[14]=t.z; w2r[15]=t.w;
  }
  const float b2v = b2[0];

  float logit_keep = 0.f;
  #pragma unroll
  for (int s = 0; s < SPW; s += 2){
    const int na = n0 + s, nb = n0 + s + 1;
    const int ia = bids[na], ga = begins[na], ea = ends[na];
    const int ib = bids[nb], gb = begins[nb], eb = ends[nb];
    const uint4* PeA = reinterpret_cast<const uint4*>(g_P + ((size_t)(ea*32+ia))*512u);
    const uint4* PgA = reinterpret_cast<const uint4*>(g_P + ((size_t)(ga*32+ia))*512u);
    const uint4* PeB = reinterpret_cast<const uint4*>(g_P + ((size_t)(eb*32+ib))*512u);
    const uint4* PgB = reinterpret_cast<const uint4*>(g_P + ((size_t)(gb*32+ib))*512u);
    uint4 a0 = PeA[lane], a1 = PeA[lane+32];
    uint4 c0 = PgA[lane], c1 = PgA[lane+32];
    uint4 d0 = PeB[lane], d1 = PeB[lane+32];
    uint4 f0 = PgB[lane], f1 = PgB[lane+32];
    float acca = proc8(a0, c0, b1r,   w2r,   0.f);
    acca       = proc8(a1, c1, b1r+8, w2r+8, acca);
    float accb = proc8(d0, f0, b1r,   w2r,   0.f);
    accb       = proc8(d1, f1, b1r+8, w2r+8, accb);
    #pragma unroll
    for (int off=16; off>0; off>>=1){
      acca += __shfl_xor_sync(0xffffffffu, acca, off);
      accb += __shfl_xor_sync(0xffffffffu, accb, off);
    }
    if (lane == s)   logit_keep = acca;
    if (lane == s+1) logit_keep = accb;
  }

  // lanes 0..SPW-1 each own one span's logit
  float sp = 0.f, sn = 0.f, sc = 0.f;
  if (lane < SPW){
    const int n = n0 + lane;
    float logit = logit_keep + b2v;
    float pp = 1.f / (1.f + expf(-logit));
    pp = fminf(fmaxf(pp, 1e-7f), 1.f - 1e-7f);
    int fl = flags[n];
    float wgt = wts[n];
    float bce = (fl == 1) ? -logf(pp) : -logf(1.f - pp);
    sp = (fl == 1) ? wgt*bce : 0.f;
    sn = (fl == 1) ? 0.f : wgt*bce;
    sc = (fl == 1) ? 1.f : 0.f;
  }
  #pragma unroll
  for (int off=16; off>0; off>>=1){
    sp += __shfl_xor_sync(0xffffffffu, sp, off);
    sn += __shfl_xor_sync(0xffffffffu, sn, off);
    sc += __shfl_xor_sync(0xffffffffu, sc, off);
  }
  if (lane == 0){ s_red[wrp][0]=sp; s_red[wrp][1]=sn; s_red[wrp][2]=sc; }
  __syncthreads();
  if (threadIdx.x == 0){
    float a=0.f,b=0.f,c=0.f;
    #pragma unroll
    for (int i=0;i<8;i++){ a+=s_red[i][0]; b+=s_red[i][1]; c+=s_red[i][2]; }
    g_part[blockIdx.x*3+0]=a;
    g_part[blockIdx.x*3+1]=b;
    g_part[blockIdx.x*3+2]=c;
  }
}

// ---------------- deterministic final reduction ----------------
__global__ void finalize_kernel(float* __restrict__ out){
  __shared__ float sp[256], sn[256], sc[256];
  int t = threadIdx.x;
  float a=0.f, b=0.f, c=0.f;
  for (int i=t; i<SPAN_BLOCKS; i+=256){
    a += g_part[i*3+0];
    b += g_part[i*3+1];
    c += g_part[i*3+2];
  }
  sp[t]=a; sn[t]=b; sc[t]=c;
  __syncthreads();
  for (int s=128; s>0; s>>=1){
    if (t < s){ sp[t]+=sp[t+s]; sn[t]+=sn[t+s]; sc[t]+=sc[t+s]; }
    __syncthreads();
  }
  if (t==0){
    const float Nf = 131072.f;
    float scale = 2.f*sc[0]/Nf;
    out[0] = (sp[0] + scale*sn[0]) / Nf;
  }
}

// ---------------- launch ----------------
extern "C" void kernel_launch(void* const* d_in, const int* in_sizes, int n_in,
                              void* d_out, int out_size){
  const float* hidden = (const float*)d_in[0];
  const int* bids     = (const int*)d_in[1];
  const int* begins   = (const int*)d_in[2];
  const int* ends     = (const int*)d_in[3];
  const int* flags    = (const int*)d_in[4];
  const float* wts    = (const float*)d_in[5];
  const float* W1     = (const float*)d_in[6];
  const float* b1     = (const float*)d_in[7];
  const float* W2     = (const float*)d_in[8];
  const float* b2     = (const float*)d_in[9];

  conv_hidden_kernel<<<8192, 256>>>(hidden);
  conv_w_kernel<<<2048, 256>>>(W1);
  gemm_kernel<<<dim3(NDIM/BN, MROWS/BM), 256>>>();
  span_kernel<<<SPAN_BLOCKS, 256>>>(bids, begins, ends, flags, wts, b1, W2, b2);
  finalize_kernel<<<1, 256>>>((float*)d_out);
}

// round 6
// speedup vs baseline: 1.3773x; 1.0333x over previous
#include <cuda_runtime.h>
#include <cuda_bf16.h>
#include <stdint.h>

#define S_LEN  512
#define BATCH  32
#define NSPAN  131072
#define MROWS  16384   // S*B
#define KDIM   1024
#define NDIM   512

#define BM 128
#define BN 256
#define BK 32
#define NSTG 4
#define NIT  (KDIM/BK)            // 32
#define LDSB 40                   // smem row stride in bf16 (32 + 8 pad)
#define A_STG_BYTES (BM*LDSB*2)   // 10240
#define B_STG_BYTES (BN*LDSB*2)   // 20480
#define GEMM_SMEM (NSTG*(A_STG_BYTES+B_STG_BYTES))   // 122880

#define SPW 16   // spans per warp in span_kernel
#define SPAN_BLOCKS (NSPAN / (8 * SPW))   // 1024

// ---- scratch (static device globals; no runtime allocation) ----
__device__ __align__(256) __nv_bfloat16 g_A[(size_t)MROWS*KDIM];  // 32 MB: A2[m][k]
__device__ __align__(256) __nv_bfloat16 g_W[(size_t)NDIM*KDIM];   //  1 MB: W'[n][k]
__device__ __align__(256) __nv_bfloat16 g_P[(size_t)MROWS*NDIM];  // 16 MB: P[m][n]
__device__ float g_part[SPAN_BLOCKS*3];
__device__ unsigned g_ctr;

// ---------------- build A2 = [Hf[r-1] , Hb[r]] in bf16 (one pass) ----------------
__global__ void conv_hidden_kernel(const float* __restrict__ hidden){
  unsigned idx = blockIdx.x*256u + threadIdx.x;   // 16384*128
  unsigned c8 = idx & 127u;
  unsigned m  = idx >> 7;
  unsigned r  = m >> 5;
  unsigned b  = m & 31u;
  unsigned col = c8 * 8u;
  __nv_bfloat162 o0, o1, o2, o3;
  if (col < 512u){
    if (r == 0u){
      o0 = o1 = o2 = o3 = __floats2bfloat162_rn(0.f, 0.f);
    } else {
      const float4* src = reinterpret_cast<const float4*>(
          hidden + ((size_t)(r-1u)*32u + b)*1024u + col);
      float4 v0 = src[0], v1 = src[1];
      o0 = __floats2bfloat162_rn(v0.x, v0.y);
      o1 = __floats2bfloat162_rn(v0.z, v0.w);
      o2 = __floats2bfloat162_rn(v1.x, v1.y);
      o3 = __floats2bfloat162_rn(v1.z, v1.w);
    }
  } else {
    const float4* src = reinterpret_cast<const float4*>(
        hidden + ((size_t)r*32u + b)*1024u + col);
    float4 v0 = src[0], v1 = src[1];
    o0 = __floats2bfloat162_rn(v0.x, v0.y);
    o1 = __floats2bfloat162_rn(v0.z, v0.w);
    o2 = __floats2bfloat162_rn(v1.x, v1.y);
    o3 = __floats2bfloat162_rn(v1.z, v1.w);
  }
  uint4 pack;
  pack.x = *reinterpret_cast<uint32_t*>(&o0);
  pack.y = *reinterpret_cast<uint32_t*>(&o1);
  pack.z = *reinterpret_cast<uint32_t*>(&o2);
  pack.w = *reinterpret_cast<uint32_t*>(&o3);
  *reinterpret_cast<uint4*>(g_A + (size_t)m*1024u + col) = pack;
}

// ---------------- W' = [W1_top ; -W1_bot] transposed -> bf16 [n][k] ----------------
__global__ void conv_w_kernel(const float* __restrict__ W1){
  unsigned idx = blockIdx.x*256u + threadIdx.x;  // 512*1024
  unsigned n = idx & 511u;
  unsigned k = idx >> 9;
  float v = W1[(size_t)k*512u + n];
  if (k >= 512u) v = -v;
  g_W[(size_t)n*1024u + k] = __float2bfloat16(v);
}

// ---------------- mma.sync helpers ----------------
__device__ __forceinline__ void mma_bf16(float* d, const uint32_t* a, const uint32_t* b){
  asm volatile(
    "mma.sync.aligned.m16n8k16.row.col.f32.bf16.bf16.f32 "
    "{%0,%1,%2,%3}, {%4,%5,%6,%7}, {%8,%9}, {%0,%1,%2,%3};\n"
    : "+f"(d[0]), "+f"(d[1]), "+f"(d[2]), "+f"(d[3])
    : "r"(a[0]), "r"(a[1]), "r"(a[2]), "r"(a[3]), "r"(b[0]), "r"(b[1]));
}
__device__ __forceinline__ void ldsm_x4(uint32_t* r, uint32_t addr){
  asm volatile("ldmatrix.sync.aligned.m8n8.x4.shared.b16 {%0,%1,%2,%3}, [%4];\n"
    : "=r"(r[0]), "=r"(r[1]), "=r"(r[2]), "=r"(r[3]) : "r"(addr));
}
__device__ __forceinline__ void cpa16(uint32_t dst, const void* src){
  asm volatile("cp.async.cg.shared.global [%0], [%1], 16;\n" :: "r"(dst), "l"(src));
}
__device__ __forceinline__ void cpa_commit(){
  asm volatile("cp.async.commit_group;\n");
}
__device__ __forceinline__ void cpa_wait2(){
  asm volatile("cp.async.wait_group 2;\n");
}

// ---------------- multistage cp.async GEMM: P = A2 @ W'^T ----------------
extern __shared__ char dsm[];
__global__ __launch_bounds__(256) void gemm_kernel(){
  const int tid  = threadIdx.x;
  const int lane = tid & 31;
  const int w    = tid >> 5;
  const int wm   = w & 1;    // 2 warps along M (64 rows)
  const int wn   = w >> 1;   // 4 warps along N (64 cols)

  const __nv_bfloat16* __restrict__ Ag = g_A + (size_t)blockIdx.y*BM*KDIM;
  const __nv_bfloat16* __restrict__ Bg = g_W + (size_t)blockIdx.x*BN*KDIM;

  uint32_t sbase = (uint32_t)__cvta_generic_to_shared(dsm);
  uint32_t aS[NSTG], bS[NSTG];
  #pragma unroll
  for (int s=0;s<NSTG;s++){
    aS[s] = sbase + s*A_STG_BYTES;
    bS[s] = sbase + NSTG*A_STG_BYTES + s*B_STG_BYTES;
  }

  // cp.async thread mapping
  const int ar0 = tid >> 2;            // A rows: ar0, ar0+64
  const int ach = (tid & 3) * 8;       // element offset of 16B chunk
  const int br0 = tid >> 2;            // B rows: br0 + 64*i, i<4
  const int bch = (tid & 3) * 8;

  // ldmatrix lane addressing (element offsets within a stage)
  const int a_row = wm*64 + (lane & 15);
  const int a_chL = (lane >> 4) * 8;
  const int b_row = wn*64 + (lane & 7);
  const int b_chL = ((lane >> 3) & 3) * 8;   // covers all 32 k of the chunk

  float acc[4][8][4];
  #pragma unroll
  for (int i=0;i<4;i++)
    #pragma unroll
    for (int j=0;j<8;j++)
      #pragma unroll
      for (int q=0;q<4;q++) acc[i][j][q]=0.f;

  // prologue: issue stages 0..2
  #pragma unroll
  for (int s=0; s<NSTG-1; s++){
    int k0 = s*BK;
    #pragma unroll
    for (int i=0;i<2;i++){
      int row = ar0 + i*64;
      cpa16(aS[s] + (uint32_t)(row*LDSB + ach)*2u,
            Ag + (size_t)row*KDIM + k0 + ach);
    }
    #pragma unroll
    for (int i=0;i<4;i++){
      int row = br0 + i*64;
      cpa16(bS[s] + (uint32_t)(row*LDSB + bch)*2u,
            Bg + (size_t)row*KDIM + k0 + bch);
    }
    cpa_commit();
  }

  for (int it = 0; it < NIT; it++){
    cpa_wait2();
    __syncthreads();
    // issue stage it+3
    if (it + NSTG - 1 < NIT){
      int s = (it + NSTG - 1) & (NSTG-1);
      int k0 = (it + NSTG - 1)*BK;
      #pragma unroll
      for (int i=0;i<2;i++){
        int row = ar0 + i*64;
        cpa16(aS[s] + (uint32_t)(row*LDSB + ach)*2u,
              Ag + (size_t)row*KDIM + k0 + ach);
      }
      #pragma unroll
      for (int i=0;i<4;i++){
        int row = br0 + i*64;
        cpa16(bS[s] + (uint32_t)(row*LDSB + bch)*2u,
              Bg + (size_t)row*KDIM + k0 + bch);
      }
    }
    cpa_commit();

    // compute stage it
    const int s = it & (NSTG-1);
    uint32_t aL = aS[s] + (uint32_t)(a_row*LDSB + a_chL)*2u;
    uint32_t bL = bS[s] + (uint32_t)(b_row*LDSB + b_chL)*2u;

    uint32_t bf[8][4];
    #pragma unroll
    for (int nt=0; nt<8; nt++)
      ldsm_x4(bf[nt], bL + (uint32_t)(nt*8*LDSB*2));
    #pragma unroll
    for (int kk=0; kk<2; kk++){
      uint32_t af[4][4];
      #pragma unroll
      for (int mt=0; mt<4; mt++)
        ldsm_x4(af[mt], aL + (uint32_t)(mt*16*LDSB*2) + (uint32_t)(kk*16*2));
      #pragma unroll
      for (int mt=0; mt<4; mt++)
        #pragma unroll
        for (int nt=0; nt<8; nt++)
          mma_bf16(acc[mt][nt], af[mt], &bf[nt][kk*2]);
    }
    __syncthreads();
  }

  // epilogue: bf16 P
  const int rbase = blockIdx.y*BM + wm*64;
  const int cbase = blockIdx.x*BN + wn*64;
  #pragma unroll
  for (int mt=0; mt<4; mt++){
    int r0 = rbase + mt*16 + (lane >> 2);
    #pragma unroll
    for (int nt=0; nt<8; nt++){
      int cc = cbase + nt*8 + (lane & 3)*2;
      __nv_bfloat162 v0 = __floats2bfloat162_rn(acc[mt][nt][0], acc[mt][nt][1]);
      __nv_bfloat162 v1 = __floats2bfloat162_rn(acc[mt][nt][2], acc[mt][nt][3]);
      *reinterpret_cast<__nv_bfloat162*>(g_P + (size_t)r0*NDIM + cc)     = v0;
      *reinterpret_cast<__nv_bfloat162*>(g_P + (size_t)(r0+8)*NDIM + cc) = v1;
    }
  }
}

// ---------------- span pass: 16 spans/warp + merged finalize ----------------
__device__ __forceinline__ float proc8(uint4 e, uint4 q,
                                        const float* __restrict__ bb,
                                        const float* __restrict__ ww, float acc){
  const uint32_t* pe = &e.x;
  const uint32_t* pq = &q.x;
  #pragma unroll
  for (int i=0;i<4;i++){
    float elo = __int_as_float(pe[i] << 16);
    float ehi = __int_as_float(pe[i] & 0xFFFF0000u);
    float qlo = __int_as_float(pq[i] << 16);
    float qhi = __int_as_float(pq[i] & 0xFFFF0000u);
    acc = fmaf(fmaxf(elo - qlo + bb[2*i],   0.f), ww[2*i],   acc);
    acc = fmaf(fmaxf(ehi - qhi + bb[2*i+1], 0.f), ww[2*i+1], acc);
  }
  return acc;
}

__global__ __launch_bounds__(256) void span_kernel(
    const int* __restrict__ bids, const int* __restrict__ begins,
    const int* __restrict__ ends, const int* __restrict__ flags,
    const float* __restrict__ wts, const float* __restrict__ b1,
    const float* __restrict__ W2, const float* __restrict__ b2,
    float* __restrict__ out)
{
  __shared__ float s_red[8][3];
  __shared__ unsigned s_rank;
  const int lane = threadIdx.x & 31;
  const int wrp  = threadIdx.x >> 5;
  const int n0   = (blockIdx.x*8 + wrp)*SPW;

  float b1r[16], w2r[16];
  {
    const float4* B1 = reinterpret_cast<const float4*>(b1);
    const float4* Wv = reinterpret_cast<const float4*>(W2);
    float4 t;
    t = B1[2*lane];    b1r[0]=t.x;  b1r[1]=t.y;  b1r[2]=t.z;  b1r[3]=t.w;
    t = B1[2*lane+1];  b1r[4]=t.x;  b1r[5]=t.y;  b1r[6]=t.z;  b1r[7]=t.w;
    t = B1[2*lane+64]; b1r[8]=t.x;  b1r[9]=t.y;  b1r[10]=t.z; b1r[11]=t.w;
    t = B1[2*lane+65]; b1r[12]=t.x; b1r[13]=t.y; b1r[14]=t.z; b1r[15]=t.w;
    t = Wv[2*lane];    w2r[0]=t.x;  w2r[1]=t.y;  w2r[2]=t.z;  w2r[3]=t.w;
    t = Wv[2*lane+1];  w2r[4]=t.x;  w2r[5]=t.y;  w2r[6]=t.z;  w2r[7]=t.w;
    t = Wv[2*lane+64]; w2r[8]=t.x;  w2r[9]=t.y;  w2r[10]=t.z; w2r[11]=t.w;
    t = Wv[2*lane+65]; w2r[12]=t.x; w2r[13]=t.y; w2r[14]=t.z; w2r[15]=t.w;
  }
  const float b2v = b2[0];

  float logit_keep = 0.f;
  #pragma unroll
  for (int s = 0; s < SPW; s += 2){
    const int na = n0 + s, nb = n0 + s + 1;
    const int ia = bids[na], ga = begins[na], ea = ends[na];
    const int ib = bids[nb], gb = begins[nb], eb = ends[nb];
    const uint4* PeA = reinterpret_cast<const uint4*>(g_P + ((size_t)(ea*32+ia))*512u);
    const uint4* PgA = reinterpret_cast<const uint4*>(g_P + ((size_t)(ga*32+ia))*512u);
    const uint4* PeB = reinterpret_cast<const uint4*>(g_P + ((size_t)(eb*32+ib))*512u);
    const uint4* PgB = reinterpret_cast<const uint4*>(g_P + ((size_t)(gb*32+ib))*512u);
    uint4 a0 = PeA[lane], a1 = PeA[lane+32];
    uint4 c0 = PgA[lane], c1 = PgA[lane+32];
    uint4 d0 = PeB[lane], d1 = PeB[lane+32];
    uint4 f0 = PgB[lane], f1 = PgB[lane+32];
    float acca = proc8(a0, c0, b1r,   w2r,   0.f);
    acca       = proc8(a1, c1, b1r+8, w2r+8, acca);
    float accb = proc8(d0, f0, b1r,   w2r,   0.f);
    accb       = proc8(d1, f1, b1r+8, w2r+8, accb);
    #pragma unroll
    for (int off=16; off>0; off>>=1){
      acca += __shfl_xor_sync(0xffffffffu, acca, off);
      accb += __shfl_xor_sync(0xffffffffu, accb, off);
    }
    if (lane == s)   logit_keep = acca;
    if (lane == s+1) logit_keep = accb;
  }

  float sp = 0.f, sn = 0.f, sc = 0.f;
  if (lane < SPW){
    const int n = n0 + lane;
    float logit = logit_keep + b2v;
    float pp = 1.f / (1.f + expf(-logit));
    pp = fminf(fmaxf(pp, 1e-7f), 1.f - 1e-7f);
    int fl = flags[n];
    float wgt = wts[n];
    float bce = (fl == 1) ? -logf(pp) : -logf(1.f - pp);
    sp = (fl == 1) ? wgt*bce : 0.f;
    sn = (fl == 1) ? 0.f : wgt*bce;
    sc = (fl == 1) ? 1.f : 0.f;
  }
  #pragma unroll
  for (int off=16; off>0; off>>=1){
    sp += __shfl_xor_sync(0xffffffffu, sp, off);
    sn += __shfl_xor_sync(0xffffffffu, sn, off);
    sc += __shfl_xor_sync(0xffffffffu, sc, off);
  }
  if (lane == 0){ s_red[wrp][0]=sp; s_red[wrp][1]=sn; s_red[wrp][2]=sc; }
  __syncthreads();
  if (threadIdx.x == 0){
    float a=0.f,b=0.f,c=0.f;
    #pragma unroll
    for (int i=0;i<8;i++){ a+=s_red[i][0]; b+=s_red[i][1]; c+=s_red[i][2]; }
    g_part[blockIdx.x*3+0]=a;
    g_part[blockIdx.x*3+1]=b;
    g_part[blockIdx.x*3+2]=c;
  }

  // merged deterministic finalize: last block reduces all partials
  __threadfence();
  if (threadIdx.x == 0) s_rank = atomicAdd(&g_ctr, 1u);
  __syncthreads();
  if (s_rank == gridDim.x - 1u){
    __threadfence();
    __shared__ float fp[256], fn[256], fc[256];
    int t = threadIdx.x;
    float a=0.f, b=0.f, c=0.f;
    for (int i=t; i<SPAN_BLOCKS; i+=256){
      a += g_part[i*3+0];
      b += g_part[i*3+1];
      c += g_part[i*3+2];
    }
    fp[t]=a; fn[t]=b; fc[t]=c;
    __syncthreads();
    for (int s=128; s>0; s>>=1){
      if (t < s){ fp[t]+=fp[t+s]; fn[t]+=fn[t+s]; fc[t]+=fc[t+s]; }
      __syncthreads();
    }
    if (t==0){
      const float Nf = 131072.f;
      float scale = 2.f*fc[0]/Nf;
      out[0] = (fp[0] + scale*fn[0]) / Nf;
      g_ctr = 0u;
    }
  }
}

// ---------------- launch ----------------
extern "C" void kernel_launch(void* const* d_in, const int* in_sizes, int n_in,
                              void* d_out, int out_size){
  const float* hidden = (const float*)d_in[0];
  const int* bids     = (const int*)d_in[1];
  const int* begins   = (const int*)d_in[2];
  const int* ends     = (const int*)d_in[3];
  const int* flags    = (const int*)d_in[4];
  const float* wts    = (const float*)d_in[5];
  const float* W1     = (const float*)d_in[6];
  const float* b1     = (const float*)d_in[7];
  const float* W2     = (const float*)d_in[8];
  const float* b2     = (const float*)d_in[9];

  static bool attr_set = false;
  if (!attr_set){
    cudaFuncSetAttribute(gemm_kernel,
                         cudaFuncAttributeMaxDynamicSharedMemorySize, GEMM_SMEM);
    attr_set = true;
  }

  conv_hidden_kernel<<<8192, 256>>>(hidden);
  conv_w_kernel<<<2048, 256>>>(W1);
  gemm_kernel<<<dim3(NDIM/BN, MROWS/BM), 256, GEMM_SMEM>>>();
  span_kernel<<<SPAN_BLOCKS, 256>>>(bids, begins, ends, flags, wts, b1, W2, b2,
                                    (float*)d_out);
}

// round 7
// speedup vs baseline: 1.5697x; 1.1397x over previous
#include <cuda_runtime.h>
#include <cuda_bf16.h>
#include <stdint.h>

#define S_LEN  512
#define BATCH  32
#define NSPAN  131072
#define MROWS  16384   // S*B
#define KDIM   1024
#define NDIM   512

#define BM 128
#define BN 128
#define BK 32
#define NSTG 3
#define NIT  (KDIM/BK)            // 32
#define LDSB 40                   // smem row stride in bf16 (32 + 8 pad)
#define A_STG_BYTES (BM*LDSB*2)   // 10240
#define B_STG_BYTES (BN*LDSB*2)   // 10240
#define GEMM_SMEM (NSTG*(A_STG_BYTES+B_STG_BYTES))   // 61440 -> 2 CTAs/SM

#define SPW 16   // spans per warp in span_kernel
#define SPAN_BLOCKS (NSPAN / (8 * SPW))   // 1024

// ---- scratch (static device globals; no runtime allocation) ----
__device__ __align__(256) __nv_bfloat16 g_A[(size_t)MROWS*KDIM];  // 32 MB: A2[m][k]
__device__ __align__(256) __nv_bfloat16 g_W[(size_t)NDIM*KDIM];   //  1 MB: W'[n][k]
__device__ __align__(256) __nv_bfloat16 g_P[(size_t)MROWS*NDIM];  // 16 MB: P[m][n]
__device__ float g_part[SPAN_BLOCKS*3];
__device__ unsigned g_ctr;

// ------- combined conversion kernel: A2 (blocks 0..8191) + W' (8192..10239) -------
__global__ void conv_kernel(const float* __restrict__ hidden,
                            const float* __restrict__ W1){
  if (blockIdx.x < 8192u){
    unsigned idx = blockIdx.x*256u + threadIdx.x;   // 16384*128
    unsigned c8 = idx & 127u;
    unsigned m  = idx >> 7;
    unsigned r  = m >> 5;
    unsigned b  = m & 31u;
    unsigned col = c8 * 8u;
    __nv_bfloat162 o0, o1, o2, o3;
    if (col < 512u){
      if (r == 0u){
        o0 = o1 = o2 = o3 = __floats2bfloat162_rn(0.f, 0.f);
      } else {
        const float4* src = reinterpret_cast<const float4*>(
            hidden + ((size_t)(r-1u)*32u + b)*1024u + col);
        float4 v0 = src[0], v1 = src[1];
        o0 = __floats2bfloat162_rn(v0.x, v0.y);
        o1 = __floats2bfloat162_rn(v0.z, v0.w);
        o2 = __floats2bfloat162_rn(v1.x, v1.y);
        o3 = __floats2bfloat162_rn(v1.z, v1.w);
      }
    } else {
      const float4* src = reinterpret_cast<const float4*>(
          hidden + ((size_t)r*32u + b)*1024u + col);
      float4 v0 = src[0], v1 = src[1];
      o0 = __floats2bfloat162_rn(v0.x, v0.y);
      o1 = __floats2bfloat162_rn(v0.z, v0.w);
      o2 = __floats2bfloat162_rn(v1.x, v1.y);
      o3 = __floats2bfloat162_rn(v1.z, v1.w);
    }
    uint4 pack;
    pack.x = *reinterpret_cast<uint32_t*>(&o0);
    pack.y = *reinterpret_cast<uint32_t*>(&o1);
    pack.z = *reinterpret_cast<uint32_t*>(&o2);
    pack.w = *reinterpret_cast<uint32_t*>(&o3);
    *reinterpret_cast<uint4*>(g_A + (size_t)m*1024u + col) = pack;
  } else {
    unsigned idx = (blockIdx.x - 8192u)*256u + threadIdx.x;  // 512*1024
    unsigned n = idx & 511u;
    unsigned k = idx >> 9;
    float v = W1[(size_t)k*512u + n];
    if (k >= 512u) v = -v;
    g_W[(size_t)n*1024u + k] = __float2bfloat16(v);
  }
}

// ---------------- mma.sync helpers ----------------
__device__ __forceinline__ void mma_bf16(float* d, const uint32_t* a, const uint32_t* b){
  asm volatile(
    "mma.sync.aligned.m16n8k16.row.col.f32.bf16.bf16.f32 "
    "{%0,%1,%2,%3}, {%4,%5,%6,%7}, {%8,%9}, {%0,%1,%2,%3};\n"
    : "+f"(d[0]), "+f"(d[1]), "+f"(d[2]), "+f"(d[3])
    : "r"(a[0]), "r"(a[1]), "r"(a[2]), "r"(a[3]), "r"(b[0]), "r"(b[1]));
}
__device__ __forceinline__ void ldsm_x4(uint32_t* r, uint32_t addr){
  asm volatile("ldmatrix.sync.aligned.m8n8.x4.shared.b16 {%0,%1,%2,%3}, [%4];\n"
    : "=r"(r[0]), "=r"(r[1]), "=r"(r[2]), "=r"(r[3]) : "r"(addr));
}
__device__ __forceinline__ void cpa16(uint32_t dst, const void* src){
  asm volatile("cp.async.cg.shared.global [%0], [%1], 16;\n" :: "r"(dst), "l"(src));
}
__device__ __forceinline__ void cpa_commit(){
  asm volatile("cp.async.commit_group;\n");
}
__device__ __forceinline__ void cpa_wait1(){
  asm volatile("cp.async.wait_group 1;\n");
}

// ---------------- 3-stage cp.async GEMM, 2 CTAs/SM: P = A2 @ W'^T ----------------
extern __shared__ char dsm[];
__global__ __launch_bounds__(256,2) void gemm_kernel(){
  const int tid  = threadIdx.x;
  const int lane = tid & 31;
  const int w    = tid >> 5;
  const int wm   = w & 1;    // 2 warps along M (64 rows)
  const int wn   = w >> 1;   // 4 warps along N (32 cols)

  const __nv_bfloat16* __restrict__ Ag = g_A + (size_t)blockIdx.y*BM*KDIM;
  const __nv_bfloat16* __restrict__ Bg = g_W + (size_t)blockIdx.x*BN*KDIM;

  uint32_t sbase = (uint32_t)__cvta_generic_to_shared(dsm);
  uint32_t aS[NSTG], bS[NSTG];
  #pragma unroll
  for (int s=0;s<NSTG;s++){
    aS[s] = sbase + s*A_STG_BYTES;
    bS[s] = sbase + NSTG*A_STG_BYTES + s*B_STG_BYTES;
  }

  const int cr0 = tid >> 2;            // rows: cr0, cr0+64
  const int cch = (tid & 3) * 8;       // element offset of 16B chunk

  const int a_row = wm*64 + (lane & 15);
  const int a_chL = (lane >> 4) * 8;
  const int b_row = wn*32 + (lane & 7);
  const int b_chL = ((lane >> 3) & 3) * 8;

  float acc[4][4][4];
  #pragma unroll
  for (int i=0;i<4;i++)
    #pragma unroll
    for (int j=0;j<4;j++)
      #pragma unroll
      for (int q=0;q<4;q++) acc[i][j][q]=0.f;

  // prologue: stages 0,1
  #pragma unroll
  for (int s=0; s<NSTG-1; s++){
    int k0 = s*BK;
    #pragma unroll
    for (int i=0;i<2;i++){
      int row = cr0 + i*64;
      cpa16(aS[s] + (uint32_t)(row*LDSB + cch)*2u, Ag + (size_t)row*KDIM + k0 + cch);
      cpa16(bS[s] + (uint32_t)(row*LDSB + cch)*2u, Bg + (size_t)row*KDIM + k0 + cch);
    }
    cpa_commit();
  }

  int cs = 0, ls = NSTG-1;
  for (int it = 0; it < NIT; it++){
    cpa_wait1();
    __syncthreads();
    if (it + NSTG - 1 < NIT){
      int k0 = (it + NSTG - 1)*BK;
      #pragma unroll
      for (int i=0;i<2;i++){
        int row = cr0 + i*64;
        cpa16(aS[ls] + (uint32_t)(row*LDSB + cch)*2u, Ag + (size_t)row*KDIM + k0 + cch);
        cpa16(bS[ls] + (uint32_t)(row*LDSB + cch)*2u, Bg + (size_t)row*KDIM + k0 + cch);
      }
    }
    cpa_commit();

    uint32_t aL = aS[cs] + (uint32_t)(a_row*LDSB + a_chL)*2u;
    uint32_t bL = bS[cs] + (uint32_t)(b_row*LDSB + b_chL)*2u;

    uint32_t bf[4][4];
    #pragma unroll
    for (int nt=0; nt<4; nt++)
      ldsm_x4(bf[nt], bL + (uint32_t)(nt*8*LDSB*2));
    #pragma unroll
    for (int kk=0; kk<2; kk++){
      uint32_t af[4][4];
      #pragma unroll
      for (int mt=0; mt<4; mt++)
        ldsm_x4(af[mt], aL + (uint32_t)(mt*16*LDSB*2) + (uint32_t)(kk*16*2));
      #pragma unroll
      for (int mt=0; mt<4; mt++)
        #pragma unroll
        for (int nt=0; nt<4; nt++)
          mma_bf16(acc[mt][nt], af[mt], &bf[nt][kk*2]);
    }
    __syncthreads();
    cs = (cs == NSTG-1) ? 0 : cs+1;
    ls = (ls == NSTG-1) ? 0 : ls+1;
  }

  const int rbase = blockIdx.y*BM + wm*64;
  const int cbase = blockIdx.x*BN + wn*32;
  #pragma unroll
  for (int mt=0; mt<4; mt++){
    int r0 = rbase + mt*16 + (lane >> 2);
    #pragma unroll
    for (int nt=0; nt<4; nt++){
      int cc = cbase + nt*8 + (lane & 3)*2;
      __nv_bfloat162 v0 = __floats2bfloat162_rn(acc[mt][nt][0], acc[mt][nt][1]);
      __nv_bfloat162 v1 = __floats2bfloat162_rn(acc[mt][nt][2], acc[mt][nt][3]);
      *reinterpret_cast<__nv_bfloat162*>(g_P + (size_t)r0*NDIM + cc)     = v0;
      *reinterpret_cast<__nv_bfloat162*>(g_P + (size_t)(r0+8)*NDIM + cc) = v1;
    }
  }
}

// ---------------- span pass: 16 spans/warp, merge-tree reduction ----------------
__device__ __forceinline__ float proc8(uint4 e, uint4 q,
                                        const float* __restrict__ bb,
                                        const float* __restrict__ ww, float acc){
  const uint32_t* pe = &e.x;
  const uint32_t* pq = &q.x;
  #pragma unroll
  for (int i=0;i<4;i++){
    float elo = __int_as_float(pe[i] << 16);
    float ehi = __int_as_float(pe[i] & 0xFFFF0000u);
    float qlo = __int_as_float(pq[i] << 16);
    float qhi = __int_as_float(pq[i] & 0xFFFF0000u);
    acc = fmaf(fmaxf(elo - qlo + bb[2*i],   0.f), ww[2*i],   acc);
    acc = fmaf(fmaxf(ehi - qhi + bb[2*i+1], 0.f), ww[2*i+1], acc);
  }
  return acc;
}

// lineage merge: lanes with (lane&m)==0 carry a-lineage, else b-lineage
__device__ __forceinline__ float mrg(float a, float b, int m, int lane){
  float d = (lane & m) ? b : a;
  float e = (lane & m) ? a : b;
  return d + __shfl_xor_sync(0xffffffffu, e, m);
}

__global__ __launch_bounds__(256) void span_kernel(
    const int* __restrict__ bids, const int* __restrict__ begins,
    const int* __restrict__ ends, const int* __restrict__ flags,
    const float* __restrict__ wts, const float* __restrict__ b1,
    const float* __restrict__ W2, const float* __restrict__ b2,
    float* __restrict__ out)
{
  __shared__ float s_red[8][3];
  __shared__ unsigned s_rank;
  const int lane = threadIdx.x & 31;
  const int wrp  = threadIdx.x >> 5;
  const int n0   = (blockIdx.x*8 + wrp)*SPW;

  float b1r[16], w2r[16];
  {
    const float4* B1 = reinterpret_cast<const float4*>(b1);
    const float4* Wv = reinterpret_cast<const float4*>(W2);
    float4 t;
    t = B1[2*lane];    b1r[0]=t.x;  b1r[1]=t.y;  b1r[2]=t.z;  b1r[3]=t.w;
    t = B1[2*lane+1];  b1r[4]=t.x;  b1r[5]=t.y;  b1r[6]=t.z;  b1r[7]=t.w;
    t = B1[2*lane+64]; b1r[8]=t.x;  b1r[9]=t.y;  b1r[10]=t.z; b1r[11]=t.w;
    t = B1[2*lane+65]; b1r[12]=t.x; b1r[13]=t.y; b1r[14]=t.z; b1r[15]=t.w;
    t = Wv[2*lane];    w2r[0]=t.x;  w2r[1]=t.y;  w2r[2]=t.z;  w2r[3]=t.w;
    t = Wv[2*lane+1];  w2r[4]=t.x;  w2r[5]=t.y;  w2r[6]=t.z;  w2r[7]=t.w;
    t = Wv[2*lane+64]; w2r[8]=t.x;  w2r[9]=t.y;  w2r[10]=t.z; w2r[11]=t.w;
    t = Wv[2*lane+65]; w2r[12]=t.x; w2r[13]=t.y; w2r[14]=t.z; w2r[15]=t.w;
  }
  const float b2v = b2[0];

  float acc[SPW];
  #pragma unroll
  for (int s = 0; s < SPW; s++){
    const int n = n0 + s;
    const int ib = bids[n], g = begins[n], e = ends[n];
    const uint4* Pe = reinterpret_cast<const uint4*>(g_P + ((size_t)(e*32+ib))*512u);
    const uint4* Pg = reinterpret_cast<const uint4*>(g_P + ((size_t)(g*32+ib))*512u);
    uint4 e0 = Pe[lane], e1 = Pe[lane+32];
    uint4 q0 = Pg[lane], q1 = Pg[lane+32];
    float a = proc8(e0, q0, b1r,   w2r,   0.f);
    acc[s]  = proc8(e1, q1, b1r+8, w2r+8, a);
  }

  // merge tree: 8+4+2+1 lineage merges + final xor16 = 16 shuffles for 16 sums
  float t1[8];
  #pragma unroll
  for (int i=0;i<8;i++) t1[i] = mrg(acc[2*i], acc[2*i+1], 1, lane);
  float t2[4];
  #pragma unroll
  for (int i=0;i<4;i++) t2[i] = mrg(t1[2*i], t1[2*i+1], 2, lane);
  float t3[2];
  #pragma unroll
  for (int i=0;i<2;i++) t3[i] = mrg(t2[2*i], t2[2*i+1], 4, lane);
  float r = mrg(t3[0], t3[1], 8, lane);
  r += __shfl_xor_sync(0xffffffffu, r, 16);
  // lane l now holds the full logit-sum for span n0 + (l & 15)

  float sp = 0.f, sn = 0.f, sc = 0.f;
  if (lane < SPW){
    const int n = n0 + lane;
    float logit = r + b2v;
    float pp = 1.f / (1.f + expf(-logit));
    pp = fminf(fmaxf(pp, 1e-7f), 1.f - 1e-7f);
    int fl = flags[n];
    float wgt = wts[n];
    float bce = (fl == 1) ? -logf(pp) : -logf(1.f - pp);
    sp = (fl == 1) ? wgt*bce : 0.f;
    sn = (fl == 1) ? 0.f : wgt*bce;
    sc = (fl == 1) ? 1.f : 0.f;
  }
  #pragma unroll
  for (int off=16; off>0; off>>=1){
    sp += __shfl_xor_sync(0xffffffffu, sp, off);
    sn += __shfl_xor_sync(0xffffffffu, sn, off);
    sc += __shfl_xor_sync(0xffffffffu, sc, off);
  }
  if (lane == 0){ s_red[wrp][0]=sp; s_red[wrp][1]=sn; s_red[wrp][2]=sc; }
  __syncthreads();
  if (threadIdx.x == 0){
    float a=0.f,b=0.f,c=0.f;
    #pragma unroll
    for (int i=0;i<8;i++){ a+=s_red[i][0]; b+=s_red[i][1]; c+=s_red[i][2]; }
    g_part[blockIdx.x*3+0]=a;
    g_part[blockIdx.x*3+1]=b;
    g_part[blockIdx.x*3+2]=c;
  }

  // merged deterministic finalize: last block reduces all partials
  __threadfence();
  if (threadIdx.x == 0) s_rank = atomicAdd(&g_ctr, 1u);
  __syncthreads();
  if (s_rank == gridDim.x - 1u){
    __threadfence();
    __shared__ float fp[256], fn[256], fc[256];
    int t = threadIdx.x;
    float a=0.f, b=0.f, c=0.f;
    for (int i=t; i<SPAN_BLOCKS; i+=256){
      a += g_part[i*3+0];
      b += g_part[i*3+1];
      c += g_part[i*3+2];
    }
    fp[t]=a; fn[t]=b; fc[t]=c;
    __syncthreads();
    for (int s=128; s>0; s>>=1){
      if (t < s){ fp[t]+=fp[t+s]; fn[t]+=fn[t+s]; fc[t]+=fc[t+s]; }
      __syncthreads();
    }
    if (t==0){
      const float Nf = 131072.f;
      float scale = 2.f*fc[0]/Nf;
      out[0] = (fp[0] + scale*fn[0]) / Nf;
      g_ctr = 0u;
    }
  }
}

// ---------------- launch ----------------
extern "C" void kernel_launch(void* const* d_in, const int* in_sizes, int n_in,
                              void* d_out, int out_size){
  const float* hidden = (const float*)d_in[0];
  const int* bids     = (const int*)d_in[1];
  const int* begins   = (const int*)d_in[2];
  const int* ends     = (const int*)d_in[3];
  const int* flags    = (const int*)d_in[4];
  const float* wts    = (const float*)d_in[5];
  const float* W1     = (const float*)d_in[6];
  const float* b1     = (const float*)d_in[7];
  const float* W2     = (const float*)d_in[8];
  const float* b2     = (const float*)d_in[9];

  static bool attr_set = false;
  if (!attr_set){
    cudaFuncSetAttribute(gemm_kernel,
                         cudaFuncAttributeMaxDynamicSharedMemorySize, GEMM_SMEM);
    attr_set = true;
  }

  conv_kernel<<<10240, 256>>>(hidden, W1);
  gemm_kernel<<<dim3(NDIM/BN, MROWS/BM), 256, GEMM_SMEM>>>();
  span_kernel<<<SPAN_BLOCKS, 256>>>(bids, begins, ends, flags, wts, b1, W2, b2,
                                    (float*)d_out);
}

// round 8
// speedup vs baseline: 1.6167x; 1.0300x over previous
#include <cuda_runtime.h>
#include <cuda_bf16.h>
#include <stdint.h>

#define S_LEN  512
#define BATCH  32
#define NSPAN  131072
#define MROWS  16384   // S*B
#define KDIM   1024
#define NDIM   512

#define BM 128
#define BN 128
#define BK 32
#define NSTG 3
#define NIT  (KDIM/BK)            // 32
#define LDSB 40                   // smem row stride in bf16 (32 + 8 pad)
#define A_STG_BYTES (BM*LDSB*2)   // 10240
#define B_STG_BYTES (BN*LDSB*2)   // 10240
#define GEMM_SMEM (NSTG*(A_STG_BYTES+B_STG_BYTES))   // 61440 -> 2 CTAs/SM

#define SPW 16   // spans per warp in span_kernel
#define SPAN_BLOCKS (NSPAN / (8 * SPW))   // 1024

// ---- scratch (static device globals; no runtime allocation) ----
__device__ __align__(256) __nv_bfloat16 g_A[(size_t)MROWS*KDIM];  // 32 MB: A2[m][k]
__device__ __align__(256) __nv_bfloat16 g_W[(size_t)NDIM*KDIM];   //  1 MB: W'[n][k]
__device__ __align__(256) __nv_bfloat16 g_P[(size_t)MROWS*NDIM];  // 16 MB: P[m][n]
__device__ float g_part[SPAN_BLOCKS*3];
__device__ unsigned g_ctr;

// ------- combined conversion: A2 (blocks 0..4095, 16 cols/thread) + W' (4096..6143) -------
__global__ void conv_kernel(const float* __restrict__ hidden,
                            const float* __restrict__ W1){
  if (blockIdx.x < 4096u){
    unsigned idx = blockIdx.x*256u + threadIdx.x;   // 16384*64
    unsigned c16 = idx & 63u;        // 16-col group (16 | 512, never straddles halves)
    unsigned m   = idx >> 6;         // row 0..16383
    unsigned r   = m >> 5;
    unsigned b   = m & 31u;
    unsigned col = c16 * 16u;
    uint4 o0 = make_uint4(0u,0u,0u,0u), o1 = o0;
    bool zero = (col < 512u) && (r == 0u);
    if (!zero){
      const float* src = (col < 512u)
          ? hidden + ((size_t)(r-1u)*32u + b)*1024u + col
          : hidden + ((size_t)r*32u + b)*1024u + col;
      float4 v0 = *reinterpret_cast<const float4*>(src);
      float4 v1 = *reinterpret_cast<const float4*>(src+4);
      float4 v2 = *reinterpret_cast<const float4*>(src+8);
      float4 v3 = *reinterpret_cast<const float4*>(src+12);
      __nv_bfloat162 t;
      t = __floats2bfloat162_rn(v0.x, v0.y); o0.x = *reinterpret_cast<uint32_t*>(&t);
      t = __floats2bfloat162_rn(v0.z, v0.w); o0.y = *reinterpret_cast<uint32_t*>(&t);
      t = __floats2bfloat162_rn(v1.x, v1.y); o0.z = *reinterpret_cast<uint32_t*>(&t);
      t = __floats2bfloat162_rn(v1.z, v1.w); o0.w = *reinterpret_cast<uint32_t*>(&t);
      t = __floats2bfloat162_rn(v2.x, v2.y); o1.x = *reinterpret_cast<uint32_t*>(&t);
      t = __floats2bfloat162_rn(v2.z, v2.w); o1.y = *reinterpret_cast<uint32_t*>(&t);
      t = __floats2bfloat162_rn(v3.x, v3.y); o1.z = *reinterpret_cast<uint32_t*>(&t);
      t = __floats2bfloat162_rn(v3.z, v3.w); o1.w = *reinterpret_cast<uint32_t*>(&t);
    }
    uint4* dst = reinterpret_cast<uint4*>(g_A + (size_t)m*1024u + col);
    dst[0] = o0; dst[1] = o1;
  } else {
    unsigned idx = (blockIdx.x - 4096u)*256u + threadIdx.x;  // 512*1024
    unsigned n = idx & 511u;
    unsigned k = idx >> 9;
    float v = W1[(size_t)k*512u + n];
    if (k >= 512u) v = -v;
    g_W[(size_t)n*1024u + k] = __float2bfloat16(v);
  }
}

// ---------------- mma.sync helpers ----------------
__device__ __forceinline__ void mma_bf16(float* d, const uint32_t* a, const uint32_t* b){
  asm volatile(
    "mma.sync.aligned.m16n8k16.row.col.f32.bf16.bf16.f32 "
    "{%0,%1,%2,%3}, {%4,%5,%6,%7}, {%8,%9}, {%0,%1,%2,%3};\n"
    : "+f"(d[0]), "+f"(d[1]), "+f"(d[2]), "+f"(d[3])
    : "r"(a[0]), "r"(a[1]), "r"(a[2]), "r"(a[3]), "r"(b[0]), "r"(b[1]));
}
__device__ __forceinline__ void ldsm_x4(uint32_t* r, uint32_t addr){
  asm volatile("ldmatrix.sync.aligned.m8n8.x4.shared.b16 {%0,%1,%2,%3}, [%4];\n"
    : "=r"(r[0]), "=r"(r[1]), "=r"(r[2]), "=r"(r[3]) : "r"(addr));
}
__device__ __forceinline__ void cpa16(uint32_t dst, const void* src){
  asm volatile("cp.async.cg.shared.global [%0], [%1], 16;\n" :: "r"(dst), "l"(src));
}
__device__ __forceinline__ void cpa_commit(){
  asm volatile("cp.async.commit_group;\n");
}
__device__ __forceinline__ void cpa_wait1(){
  asm volatile("cp.async.wait_group 1;\n");
}

// ---------------- 3-stage cp.async GEMM, 2 CTAs/SM, ONE sync/iter ----------------
extern __shared__ char dsm[];
__global__ __launch_bounds__(256,2) void gemm_kernel(){
  const int tid  = threadIdx.x;
  const int lane = tid & 31;
  const int w    = tid >> 5;
  const int wm   = w & 1;    // 2 warps along M (64 rows)
  const int wn   = w >> 1;   // 4 warps along N (32 cols)

  const __nv_bfloat16* __restrict__ Ag = g_A + (size_t)blockIdx.y*BM*KDIM;
  const __nv_bfloat16* __restrict__ Bg = g_W + (size_t)blockIdx.x*BN*KDIM;

  uint32_t sbase = (uint32_t)__cvta_generic_to_shared(dsm);
  uint32_t aS[NSTG], bS[NSTG];
  #pragma unroll
  for (int s=0;s<NSTG;s++){
    aS[s] = sbase + s*A_STG_BYTES;
    bS[s] = sbase + NSTG*A_STG_BYTES + s*B_STG_BYTES;
  }

  const int cr0 = tid >> 2;            // rows: cr0, cr0+64
  const int cch = (tid & 3) * 8;       // element offset of 16B chunk

  const int a_row = wm*64 + (lane & 15);
  const int a_chL = (lane >> 4) * 8;
  const int b_row = wn*32 + (lane & 7);
  const int b_chL = ((lane >> 3) & 3) * 8;

  float acc[4][4][4];
  #pragma unroll
  for (int i=0;i<4;i++)
    #pragma unroll
    for (int j=0;j<4;j++)
      #pragma unroll
      for (int q=0;q<4;q++) acc[i][j][q]=0.f;

  // prologue: stages 0,1
  #pragma unroll
  for (int s=0; s<NSTG-1; s++){
    int k0 = s*BK;
    #pragma unroll
    for (int i=0;i<2;i++){
      int row = cr0 + i*64;
      cpa16(aS[s] + (uint32_t)(row*LDSB + cch)*2u, Ag + (size_t)row*KDIM + k0 + cch);
      cpa16(bS[s] + (uint32_t)(row*LDSB + cch)*2u, Bg + (size_t)row*KDIM + k0 + cch);
    }
    cpa_commit();
  }

  int cs = 0, ls = NSTG-1;
  for (int it = 0; it < NIT; it++){
    cpa_wait1();
    __syncthreads();
    // safe single-sync: all threads finished READING stage (it-1)%3 before this
    // barrier, so writes into stage (it+2)%3 (same buffer) cannot race.
    if (it + NSTG - 1 < NIT){
      int k0 = (it + NSTG - 1)*BK;
      #pragma unroll
      for (int i=0;i<2;i++){
        int row = cr0 + i*64;
        cpa16(aS[ls] + (uint32_t)(row*LDSB + cch)*2u, Ag + (size_t)row*KDIM + k0 + cch);
        cpa16(bS[ls] + (uint32_t)(row*LDSB + cch)*2u, Bg + (size_t)row*KDIM + k0 + cch);
      }
    }
    cpa_commit();

    uint32_t aL = aS[cs] + (uint32_t)(a_row*LDSB + a_chL)*2u;
    uint32_t bL = bS[cs] + (uint32_t)(b_row*LDSB + b_chL)*2u;

    uint32_t bf[4][4];
    #pragma unroll
    for (int nt=0; nt<4; nt++)
      ldsm_x4(bf[nt], bL + (uint32_t)(nt*8*LDSB*2));
    #pragma unroll
    for (int kk=0; kk<2; kk++){
      uint32_t af[4][4];
      #pragma unroll
      for (int mt=0; mt<4; mt++)
        ldsm_x4(af[mt], aL + (uint32_t)(mt*16*LDSB*2) + (uint32_t)(kk*16*2));
      #pragma unroll
      for (int mt=0; mt<4; mt++)
        #pragma unroll
        for (int nt=0; nt<4; nt++)
          mma_bf16(acc[mt][nt], af[mt], &bf[nt][kk*2]);
    }
    cs = (cs == NSTG-1) ? 0 : cs+1;
    ls = (ls == NSTG-1) ? 0 : ls+1;
  }

  const int rbase = blockIdx.y*BM + wm*64;
  const int cbase = blockIdx.x*BN + wn*32;
  #pragma unroll
  for (int mt=0; mt<4; mt++){
    int r0 = rbase + mt*16 + (lane >> 2);
    #pragma unroll
    for (int nt=0; nt<4; nt++){
      int cc = cbase + nt*8 + (lane & 3)*2;
      __nv_bfloat162 v0 = __floats2bfloat162_rn(acc[mt][nt][0], acc[mt][nt][1]);
      __nv_bfloat162 v1 = __floats2bfloat162_rn(acc[mt][nt][2], acc[mt][nt][3]);
      *reinterpret_cast<__nv_bfloat162*>(g_P + (size_t)r0*NDIM + cc)     = v0;
      *reinterpret_cast<__nv_bfloat162*>(g_P + (size_t)(r0+8)*NDIM + cc) = v1;
    }
  }
}

// ---------------- span pass: 16 spans/warp, merge-tree reduction ----------------
__device__ __forceinline__ float proc8(uint4 e, uint4 q,
                                        const float* __restrict__ bb,
                                        const float* __restrict__ ww, float acc){
  const uint32_t* pe = &e.x;
  const uint32_t* pq = &q.x;
  #pragma unroll
  for (int i=0;i<4;i++){
    float elo = __int_as_float(pe[i] << 16);
    float ehi = __int_as_float(pe[i] & 0xFFFF0000u);
    float qlo = __int_as_float(pq[i] << 16);
    float qhi = __int_as_float(pq[i] & 0xFFFF0000u);
    acc = fmaf(fmaxf(elo - qlo + bb[2*i],   0.f), ww[2*i],   acc);
    acc = fmaf(fmaxf(ehi - qhi + bb[2*i+1], 0.f), ww[2*i+1], acc);
  }
  return acc;
}

__device__ __forceinline__ float mrg(float a, float b, int m, int lane){
  float d = (lane & m) ? b : a;
  float e = (lane & m) ? a : b;
  return d + __shfl_xor_sync(0xffffffffu, e, m);
}

__global__ __launch_bounds__(256) void span_kernel(
    const int* __restrict__ bids, const int* __restrict__ begins,
    const int* __restrict__ ends, const int* __restrict__ flags,
    const float* __restrict__ wts, const float* __restrict__ b1,
    const float* __restrict__ W2, const float* __restrict__ b2,
    float* __restrict__ out)
{
  __shared__ float s_red[8][3];
  __shared__ unsigned s_rank;
  const int lane = threadIdx.x & 31;
  const int wrp  = threadIdx.x >> 5;
  const int n0   = (blockIdx.x*8 + wrp)*SPW;

  float b1r[16], w2r[16];
  {
    const float4* B1 = reinterpret_cast<const float4*>(b1);
    const float4* Wv = reinterpret_cast<const float4*>(W2);
    float4 t;
    t = B1[2*lane];    b1r[0]=t.x;  b1r[1]=t.y;  b1r[2]=t.z;  b1r[3]=t.w;
    t = B1[2*lane+1];  b1r[4]=t.x;  b1r[5]=t.y;  b1r[6]=t.z;  b1r[7]=t.w;
    t = B1[2*lane+64]; b1r[8]=t.x;  b1r[9]=t.y;  b1r[10]=t.z; b1r[11]=t.w;
    t = B1[2*lane+65]; b1r[12]=t.x; b1r[13]=t.y; b1r[14]=t.z; b1r[15]=t.w;
    t = Wv[2*lane];    w2r[0]=t.x;  w2r[1]=t.y;  w2r[2]=t.z;  w2r[3]=t.w;
    t = Wv[2*lane+1];  w2r[4]=t.x;  w2r[5]=t.y;  w2r[6]=t.z;  w2r[7]=t.w;
    t = Wv[2*lane+64]; w2r[8]=t.x;  w2r[9]=t.y;  w2r[10]=t.z; w2r[11]=t.w;
    t = Wv[2*lane+65]; w2r[12]=t.x; w2r[13]=t.y; w2r[14]=t.z; w2r[15]=t.w;
  }
  const float b2v = b2[0];

  float acc[SPW];
  #pragma unroll
  for (int s = 0; s < SPW; s++){
    const int n = n0 + s;
    const int ib = bids[n], g = begins[n], e = ends[n];
    const uint4* Pe = reinterpret_cast<const uint4*>(g_P + ((size_t)(e*32+ib))*512u);
    const uint4* Pg = reinterpret_cast<const uint4*>(g_P + ((size_t)(g*32+ib))*512u);
    uint4 e0 = Pe[lane], e1 = Pe[lane+32];
    uint4 q0 = Pg[lane], q1 = Pg[lane+32];
    float a = proc8(e0, q0, b1r,   w2r,   0.f);
    acc[s]  = proc8(e1, q1, b1r+8, w2r+8, a);
  }

  float t1[8];
  #pragma unroll
  for (int i=0;i<8;i++) t1[i] = mrg(acc[2*i], acc[2*i+1], 1, lane);
  float t2[4];
  #pragma unroll
  for (int i=0;i<4;i++) t2[i] = mrg(t1[2*i], t1[2*i+1], 2, lane);
  float t3[2];
  #pragma unroll
  for (int i=0;i<2;i++) t3[i] = mrg(t2[2*i], t2[2*i+1], 4, lane);
  float r = mrg(t3[0], t3[1], 8, lane);
  r += __shfl_xor_sync(0xffffffffu, r, 16);

  float sp = 0.f, sn = 0.f, sc = 0.f;
  if (lane < SPW){
    const int n = n0 + lane;
    float logit = r + b2v;
    float pp = 1.f / (1.f + expf(-logit));
    pp = fminf(fmaxf(pp, 1e-7f), 1.f - 1e-7f);
    int fl = flags[n];
    float wgt = wts[n];
    float bce = (fl == 1) ? -logf(pp) : -logf(1.f - pp);
    sp = (fl == 1) ? wgt*bce : 0.f;
    sn = (fl == 1) ? 0.f : wgt*bce;
    sc = (fl == 1) ? 1.f : 0.f;
  }
  #pragma unroll
  for (int off=16; off>0; off>>=1){
    sp += __shfl_xor_sync(0xffffffffu, sp, off);
    sn += __shfl_xor_sync(0xffffffffu, sn, off);
    sc += __shfl_xor_sync(0xffffffffu, sc, off);
  }
  if (lane == 0){ s_red[wrp][0]=sp; s_red[wrp][1]=sn; s_red[wrp][2]=sc; }
  __syncthreads();
  if (threadIdx.x == 0){
    float a=0.f,b=0.f,c=0.f;
    #pragma unroll
    for (int i=0;i<8;i++){ a+=s_red[i][0]; b+=s_red[i][1]; c+=s_red[i][2]; }
    g_part[blockIdx.x*3+0]=a;
    g_part[blockIdx.x*3+1]=b;
    g_part[blockIdx.x*3+2]=c;
  }

  __threadfence();
  if (threadIdx.x == 0) s_rank = atomicAdd(&g_ctr, 1u);
  __syncthreads();
  if (s_rank == gridDim.x - 1u){
    __threadfence();
    __shared__ float fp[256], fn[256], fc[256];
    int t = threadIdx.x;
    float a=0.f, b=0.f, c=0.f;
    for (int i=t; i<SPAN_BLOCKS; i+=256){
      a += g_part[i*3+0];
      b += g_part[i*3+1];
      c += g_part[i*3+2];
    }
    fp[t]=a; fn[t]=b; fc[t]=c;
    __syncthreads();
    for (int s=128; s>0; s>>=1){
      if (t < s){ fp[t]+=fp[t+s]; fn[t]+=fn[t+s]; fc[t]+=fc[t+s]; }
      __syncthreads();
    }
    if (t==0){
      const float Nf = 131072.f;
      float scale = 2.f*fc[0]/Nf;
      out[0] = (fp[0] + scale*fn[0]) / Nf;
      g_ctr = 0u;
    }
  }
}

// ---------------- launch ----------------
extern "C" void kernel_launch(void* const* d_in, const int* in_sizes, int n_in,
                              void* d_out, int out_size){
  const float* hidden = (const float*)d_in[0];
  const int* bids     = (const int*)d_in[1];
  const int* begins   = (const int*)d_in[2];
  const int* ends     = (const int*)d_in[3];
  const int* flags    = (const int*)d_in[4];
  const float* wts    = (const float*)d_in[5];
  const float* W1     = (const float*)d_in[6];
  const float* b1     = (const float*)d_in[7];
  const float* W2     = (const float*)d_in[8];
  const float* b2     = (const float*)d_in[9];

  static bool attr_set = false;
  if (!attr_set){
    cudaFuncSetAttribute(gemm_kernel,
                         cudaFuncAttributeMaxDynamicSharedMemorySize, GEMM_SMEM);
    attr_set = true;
  }

  conv_kernel<<<6144, 256>>>(hidden, W1);
  gemm_kernel<<<dim3(NDIM/BN, MROWS/BM), 256, GEMM_SMEM>>>();
  span_kernel<<<SPAN_BLOCKS, 256>>>(bids, begins, ends, flags, wts, b1, W2, b2,
                                    (float*)d_out);
}